// round 3
// baseline (speedup 1.0000x reference)
#include <cuda_runtime.h>

#define NA   100000
#define NB   800000
#define FEAT 64
#define HID  128
#define MAXD 32

typedef unsigned long long u64t;

// ---------------- scratch (device globals; no allocation allowed) ----------
__device__ float g_A12[(size_t)NA * 256];   // [atom][0:128]=atom@Wb1[0:64], [128:256]=atom@Wb1[64:128]
__device__ float g_cb[HID];                 // bb1 + g@Wb1[192:256]
__device__ float g_ca[HID];                 // ba1 + g@Wa1[192:256]
__device__ float g_Wself[64 * HID];         // Wa1[0:64] + Wa1[128:192]
__device__ float g_bond_sum[FEAT];
__device__ float g_atom_sum[FEAT];

// ---------------- packed f32x2 helpers ------------------------------------
__device__ __forceinline__ void ffma2(u64t& d, u64t a, u64t b) {
    asm("fma.rn.f32x2 %0, %1, %2, %0;" : "+l"(d) : "l"(a), "l"(b));
}
__device__ __forceinline__ u64t pack2(float x, float y) {
    u64t r; asm("mov.b64 %0, {%1, %2};" : "=l"(r) : "f"(x), "f"(y)); return r;
}
__device__ __forceinline__ u64t pack1(float x) {
    u64t r; asm("mov.b64 %0, {%1, %1};" : "=l"(r) : "f"(x)); return r;
}
__device__ __forceinline__ float2 unpk(u64t v) {
    float2 f; asm("mov.b64 {%0, %1}, %2;" : "=f"(f.x), "=f"(f.y) : "l"(v)); return f;
}

__device__ __forceinline__ float softplus_f(float x) {
    // == jnp.logaddexp(x, 0) = max(x,0) + log1p(exp(-|x|))
    return fmaxf(x, 0.0f) + log1pf(__expf(-fabsf(x)));
}

// ---------------- K0: constants / zero accumulators ------------------------
__global__ void k0_prep(const float* __restrict__ g,
                        const float* __restrict__ Wb1, const float* __restrict__ bb1,
                        const float* __restrict__ Wa1, const float* __restrict__ ba1) {
    int t = threadIdx.x;  // 128 threads
    float cb = bb1[t], ca = ba1[t];
#pragma unroll 8
    for (int f = 0; f < 64; f++) {
        float gv = g[f];
        cb += gv * Wb1[(192 + f) * HID + t];
        ca += gv * Wa1[(192 + f) * HID + t];
    }
    g_cb[t] = cb;
    g_ca[t] = ca;
    if (t < FEAT) { g_bond_sum[t] = 0.0f; g_atom_sum[t] = 0.0f; }
    for (int i = t; i < 64 * HID; i += 128) {
        int k = i >> 7, j = i & 127;
        g_Wself[i] = Wa1[k * HID + j] + Wa1[(128 + k) * HID + j];
    }
}

// ---------------- K1: A12 = atom_features @ [Wb1[0:64] | Wb1[64:128]] ------
// GEMM M=NA, K=64, N=256; tile = 64 atoms x 256 cols, 256 threads.
__global__ void __launch_bounds__(256, 2) k1_a12(const float* __restrict__ atom_features,
                                                 const float* __restrict__ Wb1) {
    extern __shared__ float sm[];
    float* sW = sm;            // 64*256 = 16384
    float* sA = sm + 16384;    // 64*68  = 4352 (padded rows)

    int t = threadIdx.x;
    for (int i = t; i < 16384; i += 256) {
        int k = i >> 8, n = i & 255;
        sW[i] = (n < 128) ? Wb1[k * HID + n] : Wb1[(64 + k) * HID + (n - 128)];
    }
    int row0 = blockIdx.x * 64;
#pragma unroll
    for (int r = 0; r < 4; r++) {
        int idx = t + r * 256;
        int a = idx >> 4, q = idx & 15;
        int row = row0 + a;
        float4 v = make_float4(0.f, 0.f, 0.f, 0.f);
        if (row < NA) v = *(const float4*)&atom_features[(size_t)row * FEAT + q * 4];
        *(float4*)&sA[a * 68 + q * 4] = v;
    }
    __syncthreads();

    int cg = t & 15;   // cols cg*16 .. cg*16+15
    int ag = t >> 4;   // atoms ag*4 .. ag*4+3
    u64t acc[4][8];
#pragma unroll
    for (int ai = 0; ai < 4; ai++)
#pragma unroll
        for (int p = 0; p < 8; p++) acc[ai][p] = 0ull;

    const float* wbase = sW + cg * 16;
    const float* abase = sA + (ag * 4) * 68;
#pragma unroll 4
    for (int k = 0; k < 64; k++) {
        const ulonglong2* wp = (const ulonglong2*)(wbase + (size_t)k * 256);
        ulonglong2 w0 = wp[0], w1 = wp[1], w2 = wp[2], w3 = wp[3];
#pragma unroll
        for (int ai = 0; ai < 4; ai++) {
            u64t bv = pack1(abase[ai * 68 + k]);
            ffma2(acc[ai][0], bv, w0.x); ffma2(acc[ai][1], bv, w0.y);
            ffma2(acc[ai][2], bv, w1.x); ffma2(acc[ai][3], bv, w1.y);
            ffma2(acc[ai][4], bv, w2.x); ffma2(acc[ai][5], bv, w2.y);
            ffma2(acc[ai][6], bv, w3.x); ffma2(acc[ai][7], bv, w3.y);
        }
    }
#pragma unroll
    for (int ai = 0; ai < 4; ai++) {
        int row = row0 + ag * 4 + ai;
        if (row >= NA) continue;
        float* dst = &g_A12[(size_t)row * 256 + cg * 16];
#pragma unroll
        for (int p = 0; p < 4; p++) {
            float2 a0 = unpk(acc[ai][2 * p]);
            float2 a1 = unpk(acc[ai][2 * p + 1]);
            *(float4*)(dst + p * 4) = make_float4(a0.x, a0.y, a1.x, a1.y);
        }
    }
}

// ---------------- K2: bond update (the big kernel) -------------------------
// Persistent blocks, 512 threads, 128 bonds/tile.
// h = A12[i][0:128] + A12[j][128:256] + bond@Wb1[128:192] + cb; softplus;
// out = h@Wb2 + bb2 + bond_features. Also accumulates column sums.
__global__ void __launch_bounds__(512, 1) k2_bonds(const float* __restrict__ bond_features,
                                                   const int* __restrict__ abi,
                                                   const float* __restrict__ Wb1,
                                                   const float* __restrict__ Wb2,
                                                   const float* __restrict__ bb2,
                                                   float* __restrict__ bonds_out) {
    extern __shared__ float sm[];
    float* sWmid = sm;                 // 64*128 = 8192
    float* sWb2  = sm + 8192;          // 128*64 = 8192
    float* sBond = sm + 16384;         // 128*68 = 8704
    float* sH    = sm + 25088;         // 128*132 = 16896
    int*   sIdx  = (int*)(sm + 41984); // 256 ints
    float* sSum  = sm + 42240;         // 64

    int t = threadIdx.x;
    for (int i = t; i < 8192; i += 512) sWmid[i] = Wb1[128 * HID + i];
    for (int i = t; i < 8192; i += 512) sWb2[i]  = Wb2[i];
    if (t < 64) sSum[t] = 0.0f;

    int hg = t & 15, bg = t >> 4;    // phase A: hid cols hg*8.., bonds bg*4..
    int fg = t & 7,  bg2 = t >> 3;   // phase B: out cols fg*8.., bonds bg2*2..
    float cbv[8], bb2v[8];
#pragma unroll
    for (int p = 0; p < 8; p++) { cbv[p] = g_cb[hg * 8 + p]; bb2v[p] = bb2[fg * 8 + p]; }
    float lsum[8] = {0.f, 0.f, 0.f, 0.f, 0.f, 0.f, 0.f, 0.f};
    __syncthreads();

    for (int tile = blockIdx.x; tile < NB / 128; tile += gridDim.x) {
        int b0 = tile * 128;
        if (t < 256) sIdx[t] = abi[(size_t)b0 * 2 + t];
#pragma unroll
        for (int r = 0; r < 4; r++) {
            int idx = t + r * 512;
            int b = idx >> 4, q = idx & 15;
            *(float4*)&sBond[b * 68 + q * 4] =
                *(const float4*)&bond_features[(size_t)(b0 + b) * FEAT + q * 4];
        }
        __syncthreads();

        // ---- phase A: gathered init + bond@Wmid -> hidden
        u64t acc[4][4];
#pragma unroll
        for (int bi = 0; bi < 4; bi++) {
            int b = bg * 4 + bi;
            int ai = sIdx[2 * b], aj = sIdx[2 * b + 1];
            const float4* p1 = (const float4*)&g_A12[(size_t)ai * 256 + hg * 8];
            const float4* p2 = (const float4*)&g_A12[(size_t)aj * 256 + 128 + hg * 8];
            float4 x0 = p1[0], x1 = p1[1];
            float4 y0 = p2[0], y1 = p2[1];
            acc[bi][0] = pack2(x0.x + y0.x + cbv[0], x0.y + y0.y + cbv[1]);
            acc[bi][1] = pack2(x0.z + y0.z + cbv[2], x0.w + y0.w + cbv[3]);
            acc[bi][2] = pack2(x1.x + y1.x + cbv[4], x1.y + y1.y + cbv[5]);
            acc[bi][3] = pack2(x1.z + y1.z + cbv[6], x1.w + y1.w + cbv[7]);
        }
        const float* bptr = sBond + (bg * 4) * 68;
        const float* wb = sWmid + hg * 8;
#pragma unroll 4
        for (int k = 0; k < 64; k++) {
            const ulonglong2* wp = (const ulonglong2*)(wb + k * HID);
            ulonglong2 w01 = wp[0], w23 = wp[1];
#pragma unroll
            for (int bi = 0; bi < 4; bi++) {
                u64t bv = pack1(bptr[bi * 68 + k]);
                ffma2(acc[bi][0], bv, w01.x);
                ffma2(acc[bi][1], bv, w01.y);
                ffma2(acc[bi][2], bv, w23.x);
                ffma2(acc[bi][3], bv, w23.y);
            }
        }
        // softplus + stage hidden
#pragma unroll
        for (int bi = 0; bi < 4; bi++) {
            int b = bg * 4 + bi;
            float h[8];
#pragma unroll
            for (int p = 0; p < 4; p++) {
                float2 f = unpk(acc[bi][p]);
                h[2 * p] = f.x; h[2 * p + 1] = f.y;
            }
#pragma unroll
            for (int p = 0; p < 8; p++) h[p] = softplus_f(h[p]);
            *(float4*)&sH[b * 132 + hg * 8]     = make_float4(h[0], h[1], h[2], h[3]);
            *(float4*)&sH[b * 132 + hg * 8 + 4] = make_float4(h[4], h[5], h[6], h[7]);
        }
        __syncthreads();

        // ---- phase B: out = h @ Wb2 (+ bb2 + residual)
        u64t acc2[2][4];
#pragma unroll
        for (int bi = 0; bi < 2; bi++) {
            int b = bg2 * 2 + bi;
            const float* bf = sBond + b * 68 + fg * 8;
#pragma unroll
            for (int p = 0; p < 4; p++)
                acc2[bi][p] = pack2(bb2v[2 * p] + bf[2 * p], bb2v[2 * p + 1] + bf[2 * p + 1]);
        }
        const float* hptr = sH + (bg2 * 2) * 132;
        const float* w2 = sWb2 + fg * 8;
#pragma unroll 4
        for (int k = 0; k < 128; k++) {
            const ulonglong2* wp = (const ulonglong2*)(w2 + k * 64);
            ulonglong2 w01 = wp[0], w23 = wp[1];
#pragma unroll
            for (int bi = 0; bi < 2; bi++) {
                u64t hv = pack1(hptr[bi * 132 + k]);
                ffma2(acc2[bi][0], hv, w01.x);
                ffma2(acc2[bi][1], hv, w01.y);
                ffma2(acc2[bi][2], hv, w23.x);
                ffma2(acc2[bi][3], hv, w23.y);
            }
        }
#pragma unroll
        for (int bi = 0; bi < 2; bi++) {
            int b = bg2 * 2 + bi;
            float o[8];
#pragma unroll
            for (int p = 0; p < 4; p++) {
                float2 f = unpk(acc2[bi][p]);
                o[2 * p] = f.x; o[2 * p + 1] = f.y;
            }
#pragma unroll
            for (int p = 0; p < 8; p++) lsum[p] += o[p];
            float* dst = &bonds_out[(size_t)(b0 + b) * FEAT + fg * 8];
            *(float4*)dst       = make_float4(o[0], o[1], o[2], o[3]);
            *(float4*)(dst + 4) = make_float4(o[4], o[5], o[6], o[7]);
        }
        __syncthreads();
    }
#pragma unroll
    for (int p = 0; p < 8; p++) atomicAdd(&sSum[fg * 8 + p], lsum[p]);
    __syncthreads();
    if (t < 64) atomicAdd(&g_bond_sum[t], sSum[t]);
}

// ---------------- K3: aggregation + atom update ----------------------------
// Persistent blocks, 256 threads, 32 atoms/tile.
__global__ void __launch_bounds__(256, 1) k3_atoms(const float* __restrict__ atom_features,
                                                   const int* __restrict__ bai,
                                                   const float* __restrict__ Wa1,
                                                   const float* __restrict__ Wa2,
                                                   const float* __restrict__ ba2,
                                                   const float* __restrict__ bonds_out,
                                                   float* __restrict__ atoms_out) {
    extern __shared__ float sm[];
    float* sWself = sm;                  // 8192
    float* sWagg  = sm + 8192;           // 8192 (Wa1 rows 64..127)
    float* sWa2   = sm + 16384;          // 8192
    float* sAtom  = sm + 24576;          // 32*68 = 2176
    float* sAgg   = sm + 26752;          // 2176
    float* sH     = sm + 28928;          // 32*132 = 4224
    float* sSum   = sm + 33152;          // 64
    int*   sIdxA  = (int*)(sm + 33216);  // 32*32 = 1024 ints

    int t = threadIdx.x;
    for (int i = t; i < 8192; i += 256) {
        sWself[i] = g_Wself[i];
        sWagg[i]  = Wa1[64 * HID + i];
        sWa2[i]   = Wa2[i];
    }
    if (t < 64) sSum[t] = 0.0f;

    int tq = t & 15, ta = t >> 4;   // agg phase
    int hg = t & 15, ag = t >> 4;   // hidden phase: atoms ag*2..
    int fg = t & 7,  ag2 = t >> 3;  // out phase: one atom each
    float cav[8], ba2v[8];
#pragma unroll
    for (int p = 0; p < 8; p++) { cav[p] = g_ca[hg * 8 + p]; ba2v[p] = ba2[fg * 8 + p]; }
    float lsum[8] = {0.f, 0.f, 0.f, 0.f, 0.f, 0.f, 0.f, 0.f};
    __syncthreads();

    for (int tile = blockIdx.x; tile < NA / 32; tile += gridDim.x) {
        int a0 = tile * 32;
#pragma unroll
        for (int r = 0; r < 2; r++) {
            int idx = t + r * 256;
            int a = idx >> 4, q = idx & 15;
            *(float4*)&sAtom[a * 68 + q * 4] =
                *(const float4*)&atom_features[(size_t)(a0 + a) * FEAT + q * 4];
        }
#pragma unroll
        for (int r = 0; r < 4; r++) {
            int ii = t + r * 256;
            sIdxA[ii] = bai[(size_t)a0 * MAXD + ii];
        }
        __syncthreads();

        // ---- mean aggregation of updated bonds
#pragma unroll
        for (int s = 0; s < 2; s++) {
            int a = ta + s * 16;
            float4 accv = make_float4(0.f, 0.f, 0.f, 0.f);
            int cnt = 0;
#pragma unroll 4
            for (int d = 0; d < MAXD; d++) {
                int idx = sIdxA[a * MAXD + d];
                if (idx >= 0) {
                    cnt++;
                    float4 v = *(const float4*)&bonds_out[(size_t)idx * FEAT + tq * 4];
                    accv.x += v.x; accv.y += v.y; accv.z += v.z; accv.w += v.w;
                }
            }
            float rs = 1.0f / (float)(cnt > 0 ? cnt : 1);
            accv.x *= rs; accv.y *= rs; accv.z *= rs; accv.w *= rs;
            *(float4*)&sAgg[a * 68 + tq * 4] = accv;
        }
        __syncthreads();

        // ---- hidden = atom@Wself + agg@Wagg + ca, softplus
        u64t acc[2][4];
#pragma unroll
        for (int ai = 0; ai < 2; ai++)
#pragma unroll
            for (int p = 0; p < 4; p++)
                acc[ai][p] = pack2(cav[2 * p], cav[2 * p + 1]);

        const float* atp = sAtom + (ag * 2) * 68;
        const float* agp = sAgg + (ag * 2) * 68;
        const float* w1 = sWself + hg * 8;
        const float* w2g = sWagg + hg * 8;
#pragma unroll 4
        for (int k = 0; k < 64; k++) {
            const ulonglong2* wp1 = (const ulonglong2*)(w1 + k * HID);
            const ulonglong2* wp2 = (const ulonglong2*)(w2g + k * HID);
            ulonglong2 a01 = wp1[0], a23 = wp1[1];
            ulonglong2 g01 = wp2[0], g23 = wp2[1];
#pragma unroll
            for (int ai = 0; ai < 2; ai++) {
                u64t av = pack1(atp[ai * 68 + k]);
                u64t gv = pack1(agp[ai * 68 + k]);
                ffma2(acc[ai][0], av, a01.x); ffma2(acc[ai][1], av, a01.y);
                ffma2(acc[ai][2], av, a23.x); ffma2(acc[ai][3], av, a23.y);
                ffma2(acc[ai][0], gv, g01.x); ffma2(acc[ai][1], gv, g01.y);
                ffma2(acc[ai][2], gv, g23.x); ffma2(acc[ai][3], gv, g23.y);
            }
        }
#pragma unroll
        for (int ai = 0; ai < 2; ai++) {
            int a = ag * 2 + ai;
            float h[8];
#pragma unroll
            for (int p = 0; p < 4; p++) {
                float2 f = unpk(acc[ai][p]);
                h[2 * p] = f.x; h[2 * p + 1] = f.y;
            }
#pragma unroll
            for (int p = 0; p < 8; p++) h[p] = softplus_f(h[p]);
            *(float4*)&sH[a * 132 + hg * 8]     = make_float4(h[0], h[1], h[2], h[3]);
            *(float4*)&sH[a * 132 + hg * 8 + 4] = make_float4(h[4], h[5], h[6], h[7]);
        }
        __syncthreads();

        // ---- out = h@Wa2 + ba2 + atom_features
        u64t acc2[4];
        const float* res = sAtom + ag2 * 68 + fg * 8;
#pragma unroll
        for (int p = 0; p < 4; p++)
            acc2[p] = pack2(ba2v[2 * p] + res[2 * p], ba2v[2 * p + 1] + res[2 * p + 1]);
        const float* hp = sH + ag2 * 132;
        const float* wo = sWa2 + fg * 8;
#pragma unroll 4
        for (int k = 0; k < 128; k++) {
            const ulonglong2* wp = (const ulonglong2*)(wo + k * 64);
            ulonglong2 w01 = wp[0], w23 = wp[1];
            u64t hv = pack1(hp[k]);
            ffma2(acc2[0], hv, w01.x); ffma2(acc2[1], hv, w01.y);
            ffma2(acc2[2], hv, w23.x); ffma2(acc2[3], hv, w23.y);
        }
        {
            float o[8];
#pragma unroll
            for (int p = 0; p < 4; p++) {
                float2 f = unpk(acc2[p]);
                o[2 * p] = f.x; o[2 * p + 1] = f.y;
            }
#pragma unroll
            for (int p = 0; p < 8; p++) lsum[p] += o[p];
            float* dst = &atoms_out[(size_t)(a0 + ag2) * FEAT + fg * 8];
            *(float4*)dst       = make_float4(o[0], o[1], o[2], o[3]);
            *(float4*)(dst + 4) = make_float4(o[4], o[5], o[6], o[7]);
        }
        __syncthreads();
    }
#pragma unroll
    for (int p = 0; p < 8; p++) atomicAdd(&sSum[fg * 8 + p], lsum[p]);
    __syncthreads();
    if (t < 64) atomicAdd(&g_atom_sum[t], sSum[t]);
}

// ---------------- K4: global update ----------------------------------------
__global__ void k4_global(const float* __restrict__ g,
                          const float* __restrict__ Wg1, const float* __restrict__ bg1,
                          const float* __restrict__ Wg2, const float* __restrict__ bg2,
                          float* __restrict__ out_global) {
    __shared__ float comb[192];
    __shared__ float sh[128];
    int t = threadIdx.x;  // 192 threads
    if (t < 64)       comb[t] = g_atom_sum[t] * (1.0f / (float)NA);
    else if (t < 128) comb[t] = g_bond_sum[t - 64] * (1.0f / (float)NB);
    else              comb[t] = g[t - 128];
    __syncthreads();
    if (t < 128) {
        float a = bg1[t];
#pragma unroll 8
        for (int k = 0; k < 192; k++) a += comb[k] * Wg1[k * HID + t];
        sh[t] = softplus_f(a);
    }
    __syncthreads();
    if (t < 64) {
        float a = bg2[t] + g[t];
#pragma unroll 8
        for (int k = 0; k < 128; k++) a += sh[k] * Wg2[k * 64 + t];
        out_global[t] = a;
    }
}

// ---------------- launch ----------------------------------------------------
extern "C" void kernel_launch(void* const* d_in, const int* in_sizes, int n_in,
                              void* d_out, int out_size) {
    const float* atom_features = (const float*)d_in[0];
    const float* bond_features = (const float*)d_in[1];
    const float* gfeat         = (const float*)d_in[2];
    const float* Wb1 = (const float*)d_in[3];
    const float* bb1 = (const float*)d_in[4];
    const float* Wb2 = (const float*)d_in[5];
    const float* bb2 = (const float*)d_in[6];
    const float* Wa1 = (const float*)d_in[7];
    const float* ba1 = (const float*)d_in[8];
    const float* Wa2 = (const float*)d_in[9];
    const float* ba2 = (const float*)d_in[10];
    const float* Wg1 = (const float*)d_in[11];
    const float* bg1 = (const float*)d_in[12];
    const float* Wg2 = (const float*)d_in[13];
    const float* bg2 = (const float*)d_in[14];
    const int* abi = (const int*)d_in[15];
    const int* bai = (const int*)d_in[16];

    float* out        = (float*)d_out;
    float* atoms_out  = out;
    float* bonds_out  = out + (size_t)NA * FEAT;
    float* global_out = out + (size_t)NA * FEAT + (size_t)NB * FEAT;

    const int smem1 = 20736 * 4;              // 82,944 B
    const int smem2 = 42304 * 4;              // 169,216 B
    const int smem3 = 33216 * 4 + 1024 * 4;   // 136,960 B
    cudaFuncSetAttribute(k1_a12,   cudaFuncAttributeMaxDynamicSharedMemorySize, smem1);
    cudaFuncSetAttribute(k2_bonds, cudaFuncAttributeMaxDynamicSharedMemorySize, smem2);
    cudaFuncSetAttribute(k3_atoms, cudaFuncAttributeMaxDynamicSharedMemorySize, smem3);

    k0_prep<<<1, 128>>>(gfeat, Wb1, bb1, Wa1, ba1);
    k1_a12<<<(NA + 63) / 64, 256, smem1>>>(atom_features, Wb1);
    k2_bonds<<<148, 512, smem2>>>(bond_features, abi, Wb1, Wb2, bb2, bonds_out);
    k3_atoms<<<148, 256, smem3>>>(atom_features, bai, Wa1, Wa2, ba2, bonds_out, atoms_out);
    k4_global<<<1, 192>>>(gfeat, Wg1, bg1, Wg2, bg2, global_out);
}